// round 9
// baseline (speedup 1.0000x reference)
#include <cuda_runtime.h>
#include <cuda_bf16.h>
#include <math_constants.h>

// GaussianConditionalStanh: fused quantize(symbols) + dequantize.
//   y = inputs - means
//   idx = searchsorted(mid, y), side='left'  (count of mid < y)
//   out[0:N]  = (float)idx
//   out[N:2N] = codebook[idx] + means
//
// R5: same affine guess + fixed 2-probe correction as R4, but the two
// midpoint probes (smid[g0], smid[g0+1]) come from a float2 pair table
// -> single LDS.64 instead of two LDS.32. Fallback binary search kept
// for arbitrary sorted codebooks (runtime-verified affine precondition).

#define L_CODE 60
#define NMID   59

__global__ __launch_bounds__(256)
void gcs_kernel(const float4* __restrict__ x4,
                const float4* __restrict__ m4,
                const float*  __restrict__ codebook,
                float4* __restrict__ sym4,
                float4* __restrict__ dq4,
                int n4)
{
    __shared__ float  sc[L_CODE];        // codebook values
    __shared__ float  smid[NMID + 1];    // midpoints, smid[59] = +INF
    __shared__ float2 pmid[NMID];        // pmid[k] = (smid[k], smid[k+1])
    __shared__ int    sBad;

    if (threadIdx.x == 0) sBad = 0;
    if (threadIdx.x < L_CODE)
        sc[threadIdx.x] = codebook[threadIdx.x];
    __syncthreads();
    if (threadIdx.x < NMID)
        smid[threadIdx.x] = 0.5f * (sc[threadIdx.x] + sc[threadIdx.x + 1]);
    if (threadIdx.x == NMID)
        smid[NMID] = CUDART_INF_F;
    __syncthreads();
    if (threadIdx.x < NMID)
        pmid[threadIdx.x] = make_float2(smid[threadIdx.x], smid[threadIdx.x + 1]);

    const float m_lo = smid[0];
    const float inv_step = (float)(NMID - 1) / (smid[NMID - 1] - m_lo);

    // Runtime exactness check for the affine 2-probe window.
    if (threadIdx.x < NMID) {
        float u = (smid[threadIdx.x] - m_lo) * inv_step;
        if (fabsf(u - (float)threadIdx.x) > 0.998f) sBad = 1;
    }
    __syncthreads();
    const bool fast = (sBad == 0);

    int i = blockIdx.x * blockDim.x + threadIdx.x;
    int stride = gridDim.x * blockDim.x;

    for (; i < n4; i += stride) {
        float4 xv = x4[i];
        float4 mv = m4[i];

        float y0 = xv.x - mv.x;
        float y1 = xv.y - mv.y;
        float y2 = xv.z - mv.z;
        float y3 = xv.w - mv.w;

        int i0, i1, i2, i3;
        if (fast) {
            int g0 = min(max((int)floorf((y0 - m_lo) * inv_step), 0), NMID - 1);
            int g1 = min(max((int)floorf((y1 - m_lo) * inv_step), 0), NMID - 1);
            int g2 = min(max((int)floorf((y2 - m_lo) * inv_step), 0), NMID - 1);
            int g3 = min(max((int)floorf((y3 - m_lo) * inv_step), 0), NMID - 1);
            float2 p0 = pmid[g0];
            float2 p1 = pmid[g1];
            float2 p2 = pmid[g2];
            float2 p3 = pmid[g3];
            i0 = g0 + (p0.x < y0) + (p0.y < y0);
            i1 = g1 + (p1.x < y1) + (p1.y < y1);
            i2 = g2 + (p2.x < y2) + (p2.y < y2);
            i3 = g3 + (p3.x < y3) + (p3.y < y3);
        } else {
            // Exact branchless binary search fallback (any sorted codebook).
            i0 = 0; i1 = 0; i2 = 0; i3 = 0;
            #pragma unroll
            for (int step = 32; step > 0; step >>= 1) {
                int n0 = i0 + step; if (n0 <= NMID && smid[n0 - 1] < y0) i0 = n0;
                int n1 = i1 + step; if (n1 <= NMID && smid[n1 - 1] < y1) i1 = n1;
                int n2 = i2 + step; if (n2 <= NMID && smid[n2 - 1] < y2) i2 = n2;
                int n3 = i3 + step; if (n3 <= NMID && smid[n3 - 1] < y3) i3 = n3;
            }
        }

        float4 sv = make_float4((float)i0, (float)i1, (float)i2, (float)i3);
        float4 dv = make_float4(sc[i0] + mv.x, sc[i1] + mv.y,
                                sc[i2] + mv.z, sc[i3] + mv.w);
        sym4[i] = sv;
        dq4[i] = dv;
    }
}

extern "C" void kernel_launch(void* const* d_in, const int* in_sizes, int n_in,
                              void* d_out, int out_size)
{
    const float* inputs   = (const float*)d_in[0];
    const float* means    = (const float*)d_in[1];
    const float* codebook = (const float*)d_in[2];
    float* out = (float*)d_out;

    int n  = in_sizes[0];      // 28,311,552
    int n4 = n / 4;            // 7,077,888

    float* sym = out;
    float* dq  = out + n;

    const int threads = 256;
    int blocks = (n4 + threads - 1) / threads;   // 27648 exact

    gcs_kernel<<<blocks, threads>>>(
        (const float4*)inputs, (const float4*)means, codebook,
        (float4*)sym, (float4*)dq, n4);
}

// round 10
// speedup vs baseline: 1.0177x; 1.0177x over previous
#include <cuda_runtime.h>
#include <cuda_bf16.h>
#include <math_constants.h>

// GaussianConditionalStanh: fused quantize(symbols) + dequantize.
//   y = inputs - means
//   idx = searchsorted(mid, y), side='left'  (count of mid < y)
//   out[0:N]  = (float)idx
//   out[N:2N] = codebook[idx] + means
//
// R9: SINGLE-probe affine search. With u = y*inv_step + b and
// |u_k - k| <= 0.497 for all midpoints (runtime-verified), the rounded
// guess g = clamp(rn(u), 0, 58) is in {idx-1, idx}, so
//   idx = g + (mid[g] < y)   -- exact, one LDS probe.
// Violation -> uniform fallback to exact branchless binary search.

#define L_CODE 60
#define NMID   59

__global__ __launch_bounds__(256)
void gcs_kernel(const float4* __restrict__ x4,
                const float4* __restrict__ m4,
                const float*  __restrict__ codebook,
                float4* __restrict__ sym4,
                float4* __restrict__ dq4,
                int n4)
{
    __shared__ float sc[L_CODE];       // codebook values
    __shared__ float smid[NMID + 1];   // midpoints, smid[59] = +INF
    __shared__ int   sBad;

    if (threadIdx.x == 0) sBad = 0;
    if (threadIdx.x < L_CODE)
        sc[threadIdx.x] = codebook[threadIdx.x];
    __syncthreads();
    if (threadIdx.x < NMID)
        smid[threadIdx.x] = 0.5f * (sc[threadIdx.x] + sc[threadIdx.x + 1]);
    if (threadIdx.x == NMID)
        smid[NMID] = CUDART_INF_F;
    __syncthreads();

    const float m_lo = smid[0];
    const float inv_step = (float)(NMID - 1) / (smid[NMID - 1] - m_lo);
    const float bias = -m_lo * inv_step;   // u = y*inv_step + bias

    // Single-probe validity: |u_k - k| <= 0.497 for every midpoint.
    if (threadIdx.x < NMID) {
        float u = fmaf(smid[threadIdx.x], inv_step, bias);
        if (fabsf(u - (float)threadIdx.x) > 0.497f) sBad = 1;
    }
    __syncthreads();
    const bool fast = (sBad == 0);

    int i = blockIdx.x * blockDim.x + threadIdx.x;
    int stride = gridDim.x * blockDim.x;

    for (; i < n4; i += stride) {
        float4 xv = x4[i];
        float4 mv = m4[i];

        float y0 = xv.x - mv.x;
        float y1 = xv.y - mv.y;
        float y2 = xv.z - mv.z;
        float y3 = xv.w - mv.w;

        int i0, i1, i2, i3;
        if (fast) {
            int g0 = min(max(__float2int_rn(fmaf(y0, inv_step, bias)), 0), NMID - 1);
            int g1 = min(max(__float2int_rn(fmaf(y1, inv_step, bias)), 0), NMID - 1);
            int g2 = min(max(__float2int_rn(fmaf(y2, inv_step, bias)), 0), NMID - 1);
            int g3 = min(max(__float2int_rn(fmaf(y3, inv_step, bias)), 0), NMID - 1);
            i0 = g0 + (smid[g0] < y0);
            i1 = g1 + (smid[g1] < y1);
            i2 = g2 + (smid[g2] < y2);
            i3 = g3 + (smid[g3] < y3);
        } else {
            // Exact branchless binary search fallback (any sorted codebook).
            i0 = 0; i1 = 0; i2 = 0; i3 = 0;
            #pragma unroll
            for (int step = 32; step > 0; step >>= 1) {
                int n0 = i0 + step; if (n0 <= NMID && smid[n0 - 1] < y0) i0 = n0;
                int n1 = i1 + step; if (n1 <= NMID && smid[n1 - 1] < y1) i1 = n1;
                int n2 = i2 + step; if (n2 <= NMID && smid[n2 - 1] < y2) i2 = n2;
                int n3 = i3 + step; if (n3 <= NMID && smid[n3 - 1] < y3) i3 = n3;
            }
        }

        float4 sv = make_float4((float)i0, (float)i1, (float)i2, (float)i3);
        float4 dv = make_float4(sc[i0] + mv.x, sc[i1] + mv.y,
                                sc[i2] + mv.z, sc[i3] + mv.w);
        sym4[i] = sv;
        dq4[i] = dv;
    }
}

extern "C" void kernel_launch(void* const* d_in, const int* in_sizes, int n_in,
                              void* d_out, int out_size)
{
    const float* inputs   = (const float*)d_in[0];
    const float* means    = (const float*)d_in[1];
    const float* codebook = (const float*)d_in[2];
    float* out = (float*)d_out;

    int n  = in_sizes[0];      // 28,311,552
    int n4 = n / 4;            // 7,077,888

    float* sym = out;
    float* dq  = out + n;

    const int threads = 256;
    int blocks = (n4 + threads - 1) / threads;   // 27648 exact

    gcs_kernel<<<blocks, threads>>>(
        (const float4*)inputs, (const float4*)means, codebook,
        (float4*)sym, (float4*)dq, n4);
}

// round 13
// speedup vs baseline: 1.0219x; 1.0041x over previous
#include <cuda_runtime.h>
#include <cuda_bf16.h>
#include <math_constants.h>

// GaussianConditionalStanh: fused quantize(symbols) + dequantize.
//   y = inputs - means
//   idx = searchsorted(mid, y), side='left'  (count of mid < y)
//   out[0:N]  = (float)idx
//   out[N:2N] = codebook[idx] + means
//
// R10: R9's exact single-probe affine search (runtime-verified; uniform
// fallback to binary search otherwise), plus DRAM-side tuning:
//   - __ldcs / __stcs streaming cache ops (zero-reuse workload)
//   - 2x float4 per thread, loads front-batched (deeper DRAM queue)

#define L_CODE 60
#define NMID   59

__device__ __forceinline__ int probe_idx(float y, const float* __restrict__ smid,
                                         float inv_step, float bias)
{
    int g = min(max(__float2int_rn(fmaf(y, inv_step, bias)), 0), NMID - 1);
    return g + (smid[g] < y);
}

__device__ __forceinline__ int bsearch_idx(float y, const float* __restrict__ smid)
{
    int i = 0;
    #pragma unroll
    for (int step = 32; step > 0; step >>= 1) {
        int n = i + step;
        if (n <= NMID && smid[n - 1] < y) i = n;
    }
    return i;
}

__global__ __launch_bounds__(256)
void gcs_kernel(const float4* __restrict__ x4,
                const float4* __restrict__ m4,
                const float*  __restrict__ codebook,
                float4* __restrict__ sym4,
                float4* __restrict__ dq4,
                int n4)
{
    __shared__ float sc[L_CODE];       // codebook values
    __shared__ float smid[NMID + 1];   // midpoints, smid[59] = +INF
    __shared__ int   sBad;

    if (threadIdx.x == 0) sBad = 0;
    if (threadIdx.x < L_CODE)
        sc[threadIdx.x] = codebook[threadIdx.x];
    __syncthreads();
    if (threadIdx.x < NMID)
        smid[threadIdx.x] = 0.5f * (sc[threadIdx.x] + sc[threadIdx.x + 1]);
    if (threadIdx.x == NMID)
        smid[NMID] = CUDART_INF_F;
    __syncthreads();

    const float m_lo = smid[0];
    const float inv_step = (float)(NMID - 1) / (smid[NMID - 1] - m_lo);
    const float bias = -m_lo * inv_step;   // u = y*inv_step + bias

    // Single-probe validity: |u_k - k| <= 0.497 for every midpoint.
    if (threadIdx.x < NMID) {
        float u = fmaf(smid[threadIdx.x], inv_step, bias);
        if (fabsf(u - (float)threadIdx.x) > 0.497f) sBad = 1;
    }
    __syncthreads();
    const bool fast = (sBad == 0);

    int i = blockIdx.x * (blockDim.x * 2) + threadIdx.x;
    int j = i + blockDim.x;

    if (fast && j < n4) {
        // Front-batched independent 128b streaming loads (deep DRAM queue).
        float4 xa = __ldcs(&x4[i]);
        float4 xb = __ldcs(&x4[j]);
        float4 ma = __ldcs(&m4[i]);
        float4 mb = __ldcs(&m4[j]);

        float ya0 = xa.x - ma.x, ya1 = xa.y - ma.y;
        float ya2 = xa.z - ma.z, ya3 = xa.w - ma.w;
        float yb0 = xb.x - mb.x, yb1 = xb.y - mb.y;
        float yb2 = xb.z - mb.z, yb3 = xb.w - mb.w;

        int a0 = probe_idx(ya0, smid, inv_step, bias);
        int a1 = probe_idx(ya1, smid, inv_step, bias);
        int a2 = probe_idx(ya2, smid, inv_step, bias);
        int a3 = probe_idx(ya3, smid, inv_step, bias);
        int b0 = probe_idx(yb0, smid, inv_step, bias);
        int b1 = probe_idx(yb1, smid, inv_step, bias);
        int b2 = probe_idx(yb2, smid, inv_step, bias);
        int b3 = probe_idx(yb3, smid, inv_step, bias);

        float4 sa = make_float4((float)a0, (float)a1, (float)a2, (float)a3);
        float4 sb = make_float4((float)b0, (float)b1, (float)b2, (float)b3);
        float4 da = make_float4(sc[a0] + ma.x, sc[a1] + ma.y,
                                sc[a2] + ma.z, sc[a3] + ma.w);
        float4 db = make_float4(sc[b0] + mb.x, sc[b1] + mb.y,
                                sc[b2] + mb.z, sc[b3] + mb.w);

        __stcs(&sym4[i], sa);
        __stcs(&dq4[i], da);
        __stcs(&sym4[j], sb);
        __stcs(&dq4[j], db);
    } else {
        // General path: tail blocks and non-affine codebooks (exact).
        for (int k = i; k < n4; k += blockDim.x) {
            if (k != i && k != j && k >= n4) break;
            float4 xv = __ldcs(&x4[k]);
            float4 mv = __ldcs(&m4[k]);
            float y0 = xv.x - mv.x, y1 = xv.y - mv.y;
            float y2 = xv.z - mv.z, y3 = xv.w - mv.w;
            int i0, i1, i2, i3;
            if (fast) {
                i0 = probe_idx(y0, smid, inv_step, bias);
                i1 = probe_idx(y1, smid, inv_step, bias);
                i2 = probe_idx(y2, smid, inv_step, bias);
                i3 = probe_idx(y3, smid, inv_step, bias);
            } else {
                i0 = bsearch_idx(y0, smid);
                i1 = bsearch_idx(y1, smid);
                i2 = bsearch_idx(y2, smid);
                i3 = bsearch_idx(y3, smid);
            }
            float4 sv = make_float4((float)i0, (float)i1, (float)i2, (float)i3);
            float4 dv = make_float4(sc[i0] + mv.x, sc[i1] + mv.y,
                                    sc[i2] + mv.z, sc[i3] + mv.w);
            __stcs(&sym4[k], sv);
            __stcs(&dq4[k], dv);
            if (k == i) { k = j - blockDim.x; continue; }  // visit j next, then exit
            if (k == j) break;
        }
    }
}

extern "C" void kernel_launch(void* const* d_in, const int* in_sizes, int n_in,
                              void* d_out, int out_size)
{
    const float* inputs   = (const float*)d_in[0];
    const float* means    = (const float*)d_in[1];
    const float* codebook = (const float*)d_in[2];
    float* out = (float*)d_out;

    int n  = in_sizes[0];      // 28,311,552
    int n4 = n / 4;            // 7,077,888

    float* sym = out;
    float* dq  = out + n;

    const int threads = 256;
    const int per_block = threads * 2;               // 2 float4 per thread
    int blocks = (n4 + per_block - 1) / per_block;   // 13824 exact

    gcs_kernel<<<blocks, threads>>>(
        (const float4*)inputs, (const float4*)means, codebook,
        (float4*)sym, (float4*)dq, n4);
}